// round 1
// baseline (speedup 1.0000x reference)
#include <cuda_runtime.h>

#define NN      100000
#define NE      1200000
#define DIM     64
#define NG      128
#define NL      5

// Persistent scratch (device globals — no allocation).
// Zero-initialized at module load; invariants below keep agg/pool zeroed
// between invocations (mlp zeroes agg after reading; final zeroes pool).
__device__ float g_hA[NN * DIM];
__device__ float g_hB[NN * DIM];
__device__ float g_agg[NN * DIM];
__device__ float g_pool[NG * DIM];

// ---------------------------------------------------------------------------
// Edge scatter: agg[dst] += h[src].  16 threads per edge, float4 per thread,
// vector reduction (red.global.add.v4.f32, sm_90+) -> 1 REDG per 16 bytes.
// ---------------------------------------------------------------------------
__global__ void scatter_kernel(const float* __restrict__ h,
                               const int*   __restrict__ ei,
                               float*       __restrict__ agg)
{
    int i = blockIdx.x * blockDim.x + threadIdx.x;
    if (i >= NE * 16) return;
    int e = i >> 4;
    int c = i & 15;
    int s = __ldg(ei + e);        // src row
    int d = __ldg(ei + NE + e);   // dst row
    float4 v = *reinterpret_cast<const float4*>(h + (size_t)s * DIM + c * 4);
    float4* a = reinterpret_cast<float4*>(agg + (size_t)d * DIM + c * 4);
    asm volatile("red.global.add.v4.f32 [%0], {%1,%2,%3,%4};"
                 :: "l"(a), "f"(v.x), "f"(v.y), "f"(v.z), "f"(v.w)
                 : "memory");
}

// ---------------------------------------------------------------------------
// Fused MLP: z = h + agg;  y = relu((z@W1 + b1)*bn_s + bn_b);  out = relu(y@W2 + b2)
// BN folded into W1/b1 at shared-load time. One thread per node row.
// Shared: W1' [64x64], W2 [64x64], b1', b2, z tile stored [k][tid] (64x128)
// -> conflict-free scalar LDS/STS, broadcast LDS.128 on weights.
// Also zeroes agg rows after consuming them (prepares next layer's scatter).
// ---------------------------------------------------------------------------
__global__ __launch_bounds__(128)
void mlp_kernel(const float* __restrict__ h,
                float*       __restrict__ agg,
                const float* __restrict__ W1,
                const float* __restrict__ b1,
                const float* __restrict__ gamma,
                const float* __restrict__ beta,
                const float* __restrict__ W2,
                const float* __restrict__ b2,
                float*       __restrict__ hout)
{
    extern __shared__ float smem[];
    float* sW1 = smem;                    // 4096
    float* sW2 = sW1 + DIM * DIM;         // 4096
    float* sb1 = sW2 + DIM * DIM;         // 64
    float* sb2 = sb1 + DIM;               // 64
    float* sz  = sb2 + DIM;               // 64 * 128  (layout [k][tid])

    const int tid = threadIdx.x;
    const float bns = rsqrtf(1.0f + 1e-5f);

    for (int i = tid; i < DIM * DIM; i += 128) {
        int j = i & (DIM - 1);
        sW1[i] = W1[i] * (gamma[j] * bns);   // fold BN scale into W1 columns
        sW2[i] = W2[i];
    }
    if (tid < DIM) {
        sb1[tid] = b1[tid] * (gamma[tid] * bns) + beta[tid];
        sb2[tid] = b2[tid];
    }

    const int row = blockIdx.x * 128 + tid;
    if (row < NN) {
        const float4* hp = reinterpret_cast<const float4*>(h  + (size_t)row * DIM);
        float4*       ap = reinterpret_cast<float4*>(agg + (size_t)row * DIM);
        #pragma unroll
        for (int k4 = 0; k4 < 16; k4++) {
            float4 a = hp[k4];
            float4 g = ap[k4];
            sz[(4 * k4 + 0) * 128 + tid] = a.x + g.x;
            sz[(4 * k4 + 1) * 128 + tid] = a.y + g.y;
            sz[(4 * k4 + 2) * 128 + tid] = a.z + g.z;
            sz[(4 * k4 + 3) * 128 + tid] = a.w + g.w;
            ap[k4] = make_float4(0.f, 0.f, 0.f, 0.f);  // zero agg for next layer
        }
    }
    __syncthreads();
    if (row >= NN) return;

    float acc[DIM];

    // ---- GEMM1 + folded BN + ReLU ----
    #pragma unroll
    for (int j = 0; j < DIM; j++) acc[j] = sb1[j];
    for (int k = 0; k < DIM; k++) {
        float xk = sz[k * 128 + tid];
        #pragma unroll
        for (int j = 0; j < DIM; j += 4) {
            float4 w = *reinterpret_cast<const float4*>(&sW1[k * DIM + j]);
            acc[j + 0] += xk * w.x;
            acc[j + 1] += xk * w.y;
            acc[j + 2] += xk * w.z;
            acc[j + 3] += xk * w.w;
        }
    }
    #pragma unroll
    for (int j = 0; j < DIM; j++) sz[j * 128 + tid] = fmaxf(acc[j], 0.0f);

    // ---- GEMM2 + ReLU ----
    #pragma unroll
    for (int j = 0; j < DIM; j++) acc[j] = sb2[j];
    for (int k = 0; k < DIM; k++) {
        float xk = sz[k * 128 + tid];
        #pragma unroll
        for (int j = 0; j < DIM; j += 4) {
            float4 w = *reinterpret_cast<const float4*>(&sW2[k * DIM + j]);
            acc[j + 0] += xk * w.x;
            acc[j + 1] += xk * w.y;
            acc[j + 2] += xk * w.z;
            acc[j + 3] += xk * w.w;
        }
    }
    float4* op = reinterpret_cast<float4*>(hout + (size_t)row * DIM);
    #pragma unroll
    for (int j = 0; j < DIM; j += 4)
        op[j / 4] = make_float4(fmaxf(acc[j + 0], 0.f), fmaxf(acc[j + 1], 0.f),
                                fmaxf(acc[j + 2], 0.f), fmaxf(acc[j + 3], 0.f));
}

// ---------------------------------------------------------------------------
// Global add pool: pool[batch[n]] += h[n].  batch is sorted -> good L2 locality.
// ---------------------------------------------------------------------------
__global__ void pool_kernel(const float* __restrict__ h,
                            const int*   __restrict__ batch,
                            float*       __restrict__ pl)
{
    int i = blockIdx.x * blockDim.x + threadIdx.x;
    if (i >= NN * 16) return;
    int n = i >> 4;
    int c = i & 15;
    int g = __ldg(batch + n);
    float4 v = *reinterpret_cast<const float4*>(h + (size_t)n * DIM + c * 4);
    float4* a = reinterpret_cast<float4*>(pl + (size_t)g * DIM + c * 4);
    asm volatile("red.global.add.v4.f32 [%0], {%1,%2,%3,%4};"
                 :: "l"(a), "f"(v.x), "f"(v.y), "f"(v.z), "f"(v.w)
                 : "memory");
}

// ---------------------------------------------------------------------------
// Final: out = relu(pool @ lin1_w + lin1_b).  One block, thread per graph row.
// Zeroes pool after reading (prepares next invocation).
// ---------------------------------------------------------------------------
__global__ __launch_bounds__(128)
void final_kernel(float*       __restrict__ pl,
                  const float* __restrict__ W,
                  const float* __restrict__ b,
                  float*       __restrict__ out)
{
    extern __shared__ float smem[];
    float* sW = smem;             // 4096
    float* sb = sW + DIM * DIM;   // 64
    float* sx = sb + DIM;         // 64 * 128  (layout [k][tid])

    const int tid = threadIdx.x;
    for (int i = tid; i < DIM * DIM; i += 128) sW[i] = W[i];
    if (tid < DIM) sb[tid] = b[tid];

    float4* pp = reinterpret_cast<float4*>(pl + (size_t)tid * DIM);
    #pragma unroll
    for (int k4 = 0; k4 < 16; k4++) {
        float4 v = pp[k4];
        sx[(4 * k4 + 0) * 128 + tid] = v.x;
        sx[(4 * k4 + 1) * 128 + tid] = v.y;
        sx[(4 * k4 + 2) * 128 + tid] = v.z;
        sx[(4 * k4 + 3) * 128 + tid] = v.w;
        pp[k4] = make_float4(0.f, 0.f, 0.f, 0.f);   // zero pool for next call
    }
    __syncthreads();

    float acc[DIM];
    #pragma unroll
    for (int j = 0; j < DIM; j++) acc[j] = sb[j];
    for (int k = 0; k < DIM; k++) {
        float xk = sx[k * 128 + tid];
        #pragma unroll
        for (int j = 0; j < DIM; j += 4) {
            float4 w = *reinterpret_cast<const float4*>(&sW[k * DIM + j]);
            acc[j + 0] += xk * w.x;
            acc[j + 1] += xk * w.y;
            acc[j + 2] += xk * w.z;
            acc[j + 3] += xk * w.w;
        }
    }
    float* op = out + (size_t)tid * DIM;
    #pragma unroll
    for (int j = 0; j < DIM; j++) op[j] = fmaxf(acc[j], 0.0f);
}

// ---------------------------------------------------------------------------
extern "C" void kernel_launch(void* const* d_in, const int* in_sizes, int n_in,
                              void* d_out, int out_size)
{
    const float* x      = (const float*)d_in[0];
    const int*   ei     = (const int*)  d_in[1];
    const int*   batch  = (const int*)  d_in[2];
    const float* W1s    = (const float*)d_in[3];
    const float* b1s    = (const float*)d_in[4];
    const float* gammas = (const float*)d_in[5];
    const float* betas  = (const float*)d_in[6];
    const float* W2s    = (const float*)d_in[7];
    const float* b2s    = (const float*)d_in[8];
    const float* lw     = (const float*)d_in[9];
    const float* lb     = (const float*)d_in[10];
    float* out = (float*)d_out;

    float *hA, *hB, *agg, *pl;
    cudaGetSymbolAddress((void**)&hA,  g_hA);
    cudaGetSymbolAddress((void**)&hB,  g_hB);
    cudaGetSymbolAddress((void**)&agg, g_agg);
    cudaGetSymbolAddress((void**)&pl,  g_pool);

    const int mlp_smem   = (DIM * DIM * 2 + DIM * 2 + DIM * 128) * (int)sizeof(float); // 66048 B
    const int final_smem = (DIM * DIM     + DIM     + DIM * 128) * (int)sizeof(float); // 49408 B
    cudaFuncSetAttribute(mlp_kernel,   cudaFuncAttributeMaxDynamicSharedMemorySize, mlp_smem);
    cudaFuncSetAttribute(final_kernel, cudaFuncAttributeMaxDynamicSharedMemorySize, final_smem);

    const int scat_blocks = (NE * 16 + 255) / 256;   // 75000
    const int mlp_blocks  = (NN + 127) / 128;        // 782
    const int pool_blocks = (NN * 16 + 255) / 256;   // 6250

    const float* hcur = x;
    float*       hnxt = hA;
    for (int l = 0; l < NL; l++) {
        scatter_kernel<<<scat_blocks, 256>>>(hcur, ei, agg);
        mlp_kernel<<<mlp_blocks, 128, mlp_smem>>>(hcur, agg,
                                                  W1s + l * DIM * DIM, b1s + l * DIM,
                                                  gammas + l * DIM,   betas + l * DIM,
                                                  W2s + l * DIM * DIM, b2s + l * DIM,
                                                  hnxt);
        hcur = hnxt;
        hnxt = (hcur == hA) ? hB : hA;
    }

    pool_kernel<<<pool_blocks, 256>>>(hcur, batch, pl);
    final_kernel<<<1, 128, final_smem>>>(pl, lw, lb, out);
}

// round 3
// speedup vs baseline: 1.1496x; 1.1496x over previous
#include <cuda_runtime.h>

#define NN      100000
#define NE      1200000
#define DIM     64
#define NG      128
#define NL      5

// Persistent scratch (device globals — no allocation). Zero-init at load.
// Invariant: g_pool is zeroed by final_kernel after use.
__device__ float g_hA[NN * DIM];
__device__ float g_hB[NN * DIM];
__device__ float g_z[NN * DIM];       // z = h + agg, produced by gather
__device__ float g_pool[NG * DIM];
__device__ int   g_cnt[NN];           // degree counts, then reused as fill cursor
__device__ int   g_off[NN + 1];       // CSR offsets (by dst)
__device__ int   g_ssrc[NE];          // src indices sorted by dst

// ---------------------------------------------------------------------------
// Counting sort of edges by dst (edge_index is constant per launch).
// ---------------------------------------------------------------------------
__global__ void zero_cnt_kernel() {
    int i = blockIdx.x * blockDim.x + threadIdx.x;
    if (i < NN) g_cnt[i] = 0;
}

__global__ void hist_kernel(const int* __restrict__ ei) {
    int e = blockIdx.x * blockDim.x + threadIdx.x;
    if (e < NE) atomicAdd(&g_cnt[__ldg(ei + NE + e)], 1);
}

// Single-block scan: 1024 threads, each owns a chunk of ceil(NN/1024)=98.
__global__ __launch_bounds__(1024)
void scan_kernel() {
    __shared__ int part[1024];
    const int t = threadIdx.x;
    const int C = (NN + 1023) / 1024;
    const int base = t * C;
    int s = 0;
    for (int i = 0; i < C; i++) { int idx = base + i; if (idx < NN) s += g_cnt[idx]; }
    part[t] = s;
    __syncthreads();
    for (int off = 1; off < 1024; off <<= 1) {
        int v = (t >= off) ? part[t - off] : 0;
        __syncthreads();
        part[t] += v;
        __syncthreads();
    }
    int run = (t == 0) ? 0 : part[t - 1];
    for (int i = 0; i < C; i++) {
        int idx = base + i;
        if (idx < NN) {
            g_off[idx] = run;
            int c = g_cnt[idx];
            g_cnt[idx] = run;      // reuse as fill cursor
            run += c;
        }
    }
    if (t == 1023) g_off[NN] = NE;
}

__global__ void fill_kernel(const int* __restrict__ ei) {
    int e = blockIdx.x * blockDim.x + threadIdx.x;
    if (e >= NE) return;
    int d = __ldg(ei + NE + e);
    int pos = atomicAdd(&g_cnt[d], 1);
    g_ssrc[pos] = __ldg(ei + e);
}

// ---------------------------------------------------------------------------
// Gather aggregate (atomic-free): z[i] = h[i] + sum_{j in N(i)} h[j]
// 16 lanes per node (float4 each), 16 nodes per 256-thread block.
// ---------------------------------------------------------------------------
__global__ __launch_bounds__(256)
void gather_kernel(const float* __restrict__ h, float* __restrict__ z)
{
    const int tid  = threadIdx.x;
    const int lane = tid & 15;
    const int node = blockIdx.x * 16 + (tid >> 4);
    if (node >= NN) return;

    float4 acc = *reinterpret_cast<const float4*>(h + (size_t)node * DIM + lane * 4);
    const int e0 = g_off[node];
    const int e1 = g_off[node + 1];
    for (int e = e0; e < e1; e++) {
        int s = __ldg(&g_ssrc[e]);
        float4 v = *reinterpret_cast<const float4*>(h + (size_t)s * DIM + lane * 4);
        acc.x += v.x; acc.y += v.y; acc.z += v.z; acc.w += v.w;
    }
    *reinterpret_cast<float4*>(z + (size_t)node * DIM + lane * 4) = acc;
}

// ---------------------------------------------------------------------------
// Fused MLP on z: y = relu((z@W1 + b1)*bn_s + bn_b); out = relu(y@W2 + b2)
// W1/W2 overlaid in one 16KB smem slab (49.7KB total -> 4 CTAs/SM, was 3).
// sz tile is thread-private ([k][tid] layout, conflict-free).
// ---------------------------------------------------------------------------
__global__ __launch_bounds__(128)
void mlp_kernel(const float* __restrict__ z_in,
                const float* __restrict__ W1,
                const float* __restrict__ b1,
                const float* __restrict__ gamma,
                const float* __restrict__ beta,
                const float* __restrict__ W2,
                const float* __restrict__ b2,
                float*       __restrict__ hout)
{
    extern __shared__ float smem[];
    float* sW  = smem;                 // 4096 floats (16KB), W1 then W2
    float* sb1 = sW + DIM * DIM;       // 64
    float* sb2 = sb1 + DIM;            // 64
    float* sz  = sb2 + DIM;            // 64 * 128, layout [k][tid]

    const int tid = threadIdx.x;
    const float bns = rsqrtf(1.0f + 1e-5f);

    for (int i = tid; i < DIM * DIM; i += 128) {
        int j = i & (DIM - 1);
        sW[i] = W1[i] * (gamma[j] * bns);          // fold BN scale
    }
    if (tid < DIM) {
        sb1[tid] = b1[tid] * (gamma[tid] * bns) + beta[tid];
        sb2[tid] = b2[tid];
    }

    const int row = blockIdx.x * 128 + tid;
    const bool act = row < NN;
    if (act) {
        const float4* zp = reinterpret_cast<const float4*>(z_in + (size_t)row * DIM);
        #pragma unroll
        for (int k4 = 0; k4 < 16; k4++) {
            float4 v = zp[k4];
            sz[(4 * k4 + 0) * 128 + tid] = v.x;
            sz[(4 * k4 + 1) * 128 + tid] = v.y;
            sz[(4 * k4 + 2) * 128 + tid] = v.z;
            sz[(4 * k4 + 3) * 128 + tid] = v.w;
        }
    }
    __syncthreads();

    float acc[DIM];

    // ---- GEMM1 (+folded BN) + ReLU ----
    if (act) {
        #pragma unroll
        for (int j = 0; j < DIM; j++) acc[j] = sb1[j];
        #pragma unroll 4
        for (int k = 0; k < DIM; k++) {
            float xk = sz[k * 128 + tid];
            #pragma unroll
            for (int j = 0; j < DIM; j += 4) {
                float4 w = *reinterpret_cast<const float4*>(&sW[k * DIM + j]);
                acc[j + 0] += xk * w.x;
                acc[j + 1] += xk * w.y;
                acc[j + 2] += xk * w.z;
                acc[j + 3] += xk * w.w;
            }
        }
        #pragma unroll
        for (int j = 0; j < DIM; j++) sz[j * 128 + tid] = fmaxf(acc[j], 0.0f);
    }
    __syncthreads();                 // all warps done reading W1

    for (int i = tid; i < DIM * DIM; i += 128) sW[i] = W2[i];
    __syncthreads();                 // W2 visible

    // ---- GEMM2 + ReLU ----
    if (act) {
        #pragma unroll
        for (int j = 0; j < DIM; j++) acc[j] = sb2[j];
        #pragma unroll 4
        for (int k = 0; k < DIM; k++) {
            float xk = sz[k * 128 + tid];
            #pragma unroll
            for (int j = 0; j < DIM; j += 4) {
                float4 w = *reinterpret_cast<const float4*>(&sW[k * DIM + j]);
                acc[j + 0] += xk * w.x;
                acc[j + 1] += xk * w.y;
                acc[j + 2] += xk * w.z;
                acc[j + 3] += xk * w.w;
            }
        }
        float4* op = reinterpret_cast<float4*>(hout + (size_t)row * DIM);
        #pragma unroll
        for (int j = 0; j < DIM; j += 4)
            op[j / 4] = make_float4(fmaxf(acc[j + 0], 0.f), fmaxf(acc[j + 1], 0.f),
                                    fmaxf(acc[j + 2], 0.f), fmaxf(acc[j + 3], 0.f));
    }
}

// ---------------------------------------------------------------------------
// Global add pool using sortedness of batch: running segment sums, REDG flush
// only at graph boundaries. 256 threads / block, 1024 nodes / block.
// ---------------------------------------------------------------------------
__global__ __launch_bounds__(256)
void pool_kernel(const float* __restrict__ h,
                 const int*   __restrict__ batch,
                 float*       __restrict__ pl)
{
    const int tid  = threadIdx.x;
    const int lane = tid & 15;
    const int sub  = tid >> 4;
    const int base = blockIdx.x * 1024;

    float4 acc = make_float4(0.f, 0.f, 0.f, 0.f);
    int cur = -1;
    for (int i = 0; i < 64; i++) {
        int n = base + sub + i * 16;
        if (n >= NN) break;
        int g = __ldg(batch + n);
        if (g != cur) {
            if (cur >= 0) {
                float4* a = reinterpret_cast<float4*>(pl + (size_t)cur * DIM + lane * 4);
                asm volatile("red.global.add.v4.f32 [%0], {%1,%2,%3,%4};"
                             :: "l"(a), "f"(acc.x), "f"(acc.y), "f"(acc.z), "f"(acc.w)
                             : "memory");
            }
            cur = g;
            acc = make_float4(0.f, 0.f, 0.f, 0.f);
        }
        float4 v = *reinterpret_cast<const float4*>(h + (size_t)n * DIM + lane * 4);
        acc.x += v.x; acc.y += v.y; acc.z += v.z; acc.w += v.w;
    }
    if (cur >= 0) {
        float4* a = reinterpret_cast<float4*>(pl + (size_t)cur * DIM + lane * 4);
        asm volatile("red.global.add.v4.f32 [%0], {%1,%2,%3,%4};"
                     :: "l"(a), "f"(acc.x), "f"(acc.y), "f"(acc.z), "f"(acc.w)
                     : "memory");
    }
}

// ---------------------------------------------------------------------------
// Final: out = relu(pool @ lin1_w + lin1_b). Zeroes pool after reading.
// ---------------------------------------------------------------------------
__global__ __launch_bounds__(128)
void final_kernel(float*       __restrict__ pl,
                  const float* __restrict__ W,
                  const float* __restrict__ b,
                  float*       __restrict__ out)
{
    extern __shared__ float smem[];
    float* sW = smem;             // 4096 floats
    float* sb = sW + DIM * DIM;   // 64
    float* sx = sb + DIM;         // 64 * 128

    const int tid = threadIdx.x;
    for (int i = tid; i < DIM * DIM; i += 128) sW[i] = W[i];
    if (tid < DIM) sb[tid] = b[tid];

    float4* pp = reinterpret_cast<float4*>(pl + (size_t)tid * DIM);
    #pragma unroll
    for (int k4 = 0; k4 < 16; k4++) {
        float4 v = pp[k4];
        sx[(4 * k4 + 0) * 128 + tid] = v.x;
        sx[(4 * k4 + 1) * 128 + tid] = v.y;
        sx[(4 * k4 + 2) * 128 + tid] = v.z;
        sx[(4 * k4 + 3) * 128 + tid] = v.w;
        pp[k4] = make_float4(0.f, 0.f, 0.f, 0.f);   // keep pool zeroed
    }
    __syncthreads();

    float acc[DIM];
    #pragma unroll
    for (int j = 0; j < DIM; j++) acc[j] = sb[j];
    for (int k = 0; k < DIM; k++) {
        float xk = sx[k * 128 + tid];
        #pragma unroll
        for (int j = 0; j < DIM; j += 4) {
            float4 w = *reinterpret_cast<const float4*>(&sW[k * DIM + j]);
            acc[j + 0] += xk * w.x;
            acc[j + 1] += xk * w.y;
            acc[j + 2] += xk * w.z;
            acc[j + 3] += xk * w.w;
        }
    }
    float* op = out + (size_t)tid * DIM;
    #pragma unroll
    for (int j = 0; j < DIM; j++) op[j] = fmaxf(acc[j], 0.0f);
}

// ---------------------------------------------------------------------------
extern "C" void kernel_launch(void* const* d_in, const int* in_sizes, int n_in,
                              void* d_out, int out_size)
{
    const float* x      = (const float*)d_in[0];
    const int*   ei     = (const int*)  d_in[1];
    const int*   batch  = (const int*)  d_in[2];
    const float* W1s    = (const float*)d_in[3];
    const float* b1s    = (const float*)d_in[4];
    const float* gammas = (const float*)d_in[5];
    const float* betas  = (const float*)d_in[6];
    const float* W2s    = (const float*)d_in[7];
    const float* b2s    = (const float*)d_in[8];
    const float* lw     = (const float*)d_in[9];
    const float* lb     = (const float*)d_in[10];
    float* out = (float*)d_out;

    float *hA, *hB, *zb, *pl;
    cudaGetSymbolAddress((void**)&hA, g_hA);
    cudaGetSymbolAddress((void**)&hB, g_hB);
    cudaGetSymbolAddress((void**)&zb, g_z);
    cudaGetSymbolAddress((void**)&pl, g_pool);

    const int mlp_smem   = (DIM * DIM + DIM * 2 + DIM * 128) * (int)sizeof(float); // 49664 B
    const int final_smem = (DIM * DIM + DIM     + DIM * 128) * (int)sizeof(float); // 49408 B
    cudaFuncSetAttribute(mlp_kernel,   cudaFuncAttributeMaxDynamicSharedMemorySize, mlp_smem);
    cudaFuncSetAttribute(final_kernel, cudaFuncAttributeMaxDynamicSharedMemorySize, final_smem);

    // Build CSR by dst (edge_index is fixed; recomputed every call for determinism)
    zero_cnt_kernel<<<(NN + 255) / 256, 256>>>();
    hist_kernel<<<(NE + 255) / 256, 256>>>(ei);
    scan_kernel<<<1, 1024>>>();
    fill_kernel<<<(NE + 255) / 256, 256>>>(ei);

    const int gat_blocks = (NN + 15) / 16;      // 6250
    const int mlp_blocks = (NN + 127) / 128;    // 782

    const float* hcur = x;
    float*       hnxt = hA;
    for (int l = 0; l < NL; l++) {
        gather_kernel<<<gat_blocks, 256>>>(hcur, zb);
        mlp_kernel<<<mlp_blocks, 128, mlp_smem>>>(zb,
                                                  W1s + l * DIM * DIM, b1s + l * DIM,
                                                  gammas + l * DIM,   betas + l * DIM,
                                                  W2s + l * DIM * DIM, b2s + l * DIM,
                                                  hnxt);
        hcur = hnxt;
        hnxt = (hcur == hA) ? hB : hA;
    }

    pool_kernel<<<(NN + 1023) / 1024, 256>>>(hcur, batch, pl);
    final_kernel<<<1, 128, final_smem>>>(pl, lw, lb, out);
}